// round 14
// baseline (speedup 1.0000x reference)
#include <cuda_runtime.h>
#include <cuda_fp16.h>
#include <cstdint>

#define NN 50000
#define EE 800000
#define DXX 128
#define HH 8
#define DEE 32
#define FFF 512
#define EPSLN 1e-5f
#define NEGS 0.2f
#define ETOT (EE + NN)
#define MT_N 391
#define MPAD (MT_N * 128)
#define NMT (MT_N * 8)          // 16-row m-tiles

// ---------------- scratch ----------------------------------------------------
__device__ __align__(16) __half g_xlh[NN * DXX];
__device__ __align__(16) __half g_xrh[NN * DXX];
__device__ __align__(16) float g_la[NN * DEE];
__device__ __align__(16) float g_cnt[NN];
__device__ __align__(16) float g_x1[NN * DXX];
__device__ __align__(16) float g_ff[NN * DXX];
__device__ __align__(16) int   g_off[NN + 1];
__device__ __align__(16) int   g_cursor[NN];
__device__ __align__(16) int   g_csrc[ETOT];   // src per CSR slot
__device__ __align__(16) int   g_eid[ETOT];    // original edge id per CSR slot
// fp16 fragment-packed operands (m16n8k16)
__device__ __align__(16) uint32_t g_xp  [(size_t)NMT * 8 * 128];
__device__ __align__(16) uint32_t g_x1p [(size_t)NMT * 8 * 128];
__device__ __align__(16) uint32_t g_hidp[(size_t)NMT * 32 * 128];
__device__ __align__(16) uint32_t g_wlp[16 * 8 * 64];
__device__ __align__(16) uint32_t g_wrp[16 * 8 * 64];
__device__ __align__(16) uint32_t g_w1p[64 * 8 * 64];
__device__ __align__(16) uint32_t g_w2p[16 * 32 * 64];
__device__ __align__(16) uint32_t g_wep[16 * 2 * 64];

// ---------------- helpers ---------------------------------------------------
__device__ __forceinline__ uint32_t h2(float a, float b) {
    __half2 h = __floats2half2_rn(a, b);
    return *(uint32_t*)&h;
}
__device__ __forceinline__ void red_v4(float* p, float a, float b, float c, float d) {
    asm volatile("red.global.add.v4.f32 [%0], {%1,%2,%3,%4};"
                 :: "l"(p), "f"(a), "f"(b), "f"(c), "f"(d) : "memory");
}
__device__ __forceinline__ void mma_f16(float* c, const uint4& a, const uint2& b) {
    asm volatile("mma.sync.aligned.m16n8k16.row.col.f32.f16.f16.f32 "
                 "{%0,%1,%2,%3}, {%4,%5,%6,%7}, {%8,%9}, {%0,%1,%2,%3};"
                 : "+f"(c[0]), "+f"(c[1]), "+f"(c[2]), "+f"(c[3])
                 : "r"(a.x), "r"(a.y), "r"(a.z), "r"(a.w), "r"(b.x), "r"(b.y));
}
// pack one float4 (row m, cols 4q..4q+3) into A-fragment order (m16n8k16)
__device__ __forceinline__ void packA(uint32_t* Ap, int KT, int m, int q, float4 v) {
    int mt = m >> 4, mm = m & 15;
    int g = mm & 7, b0 = mm >> 3;
    int kt = q >> 2, c = q & 3;
    uint32_t* base = Ap + ((size_t)mt * KT + kt) * 128 + b0;
    int t1 = (2 * c) & 3, j1 = (2 * c) >> 2;
    base[(g * 4 + t1) * 4 + 2 * j1] = h2(v.x, v.y);
    int t2 = (2 * c + 1) & 3, j2 = (2 * c + 1) >> 2;
    base[(g * 4 + t2) * 4 + 2 * j2] = h2(v.z, v.w);
}

// ---------------- zero scratch ----------------------------------------------
__global__ void zero_kernel() {
    int t = blockIdx.x * blockDim.x + threadIdx.x;
    if (t < NN) g_cnt[t] = 0.0f;
    if (t < NN * DEE) g_la[t] = 0.0f;
}

// ---------------- degree + edge-attr sum ------------------------------------
__global__ void deg_kernel(const int* __restrict__ ei,
                           const float* __restrict__ eattr) {
    int t = blockIdx.x * blockDim.x + threadIdx.x;
    int e = t >> 3, q = t & 7;
    if (e >= EE) return;
    int dst = ei[EE + e];
    if (q == 0) atomicAdd(&g_cnt[dst], 1.0f);
    float4 v = ((const float4*)(eattr + (size_t)e * DEE))[q];
    red_v4(&g_la[(size_t)dst * DEE + q * 4], v.x, v.y, v.z, v.w);
}

__global__ void div_kernel() {
    int t = blockIdx.x * blockDim.x + threadIdx.x;
    if (t >= NN * DEE) return;
    float c = g_cnt[t >> 5];
    g_la[t] *= 1.0f / fmaxf(c, 1.0f);
}

// ---------------- CSR build -------------------------------------------------
__global__ __launch_bounds__(1024)
void scan_kernel() {
    __shared__ int part[1024];
    int t = threadIdx.x;
    int base = t * 49;
    int s = 0;
    for (int i = 0; i < 49; i++) {
        int v = base + i;
        if (v < NN) s += (int)g_cnt[v] + 1;
    }
    part[t] = s;
    __syncthreads();
    for (int ofs = 1; ofs < 1024; ofs <<= 1) {
        int v = (t >= ofs) ? part[t - ofs] : 0;
        __syncthreads();
        part[t] += v;
        __syncthreads();
    }
    int run = (t ? part[t - 1] : 0);
    for (int i = 0; i < 49; i++) {
        int v = base + i;
        if (v < NN) {
            g_off[v] = run;
            g_cursor[v] = run;
            run += (int)g_cnt[v] + 1;
        }
    }
    if (t == 1023) g_off[NN] = part[1023];
}

__global__ void scatter_kernel(const int* __restrict__ ei) {
    int e = blockIdx.x * blockDim.x + threadIdx.x;
    if (e >= ETOT) return;
    int src, dst;
    if (e < EE) { src = ei[e]; dst = ei[EE + e]; }
    else        { src = dst = e - EE; }
    int pos = atomicAdd(&g_cursor[dst], 1);
    g_csrc[pos] = src;
    g_eid[pos] = e;
}

// ---------------- pack x ----------------------------------------------------
__global__ void pack_x_kernel(const float* __restrict__ x) {
    int t = blockIdx.x * blockDim.x + threadIdx.x;
    int m = t >> 5, q = t & 31;
    if (m >= MPAD) return;
    float4 v = make_float4(0.f, 0.f, 0.f, 0.f);
    if (m < NN) v = *(const float4*)&x[(size_t)m * DXX + q * 4];
    packA(g_xp, 8, m, q, v);
}

// ---------------- pack W[K,N] -> fp16 fragment-order B ----------------------
__global__ void pack_w_kernel(const float* __restrict__ W, int K, int N, int sel) {
    uint32_t* D = (sel == 0) ? g_wlp : (sel == 1) ? g_wrp
                   : (sel == 2) ? g_w1p : (sel == 3) ? g_w2p : g_wep;
    int idx = blockIdx.x * blockDim.x + threadIdx.x;
    if (idx >= K * N) return;
    int k = idx / N, n = idx % N;
    int KT = K >> 4;
    int nt = n >> 3, g = n & 7;
    int kt = k >> 4, kk = k & 15;
    int t = (kk >> 1) & 3, j = (kk >> 3) & 1;
    size_t word = ((size_t)nt * KT + kt) * 64 + (g * 4 + t) * 2 + j;
    ((__half*)D)[word * 2 + (kk & 1)] = __float2half_rn(W[idx]);
}

// ---------------- fragment-direct fp16 GEMM ---------------------------------
// EPI: 0 = half2 store to g_xlh/g_xrh; 1 = pack g_hidp (bias+relu); 2 = f32 g_ff
template <int KT, int EPI>
__global__ __launch_bounds__(256)
void fgemm(int a_sel, int b_sel, int c_sel,
           const float* __restrict__ bias, int M, int Nc) {
    const uint32_t* Ap = (a_sel == 0) ? g_xp : (a_sel == 1) ? g_x1p : g_hidp;
    const uint32_t* Bp = (b_sel == 0) ? g_wlp : (b_sel == 1) ? g_wrp
                          : (b_sel == 2) ? g_w1p : g_w2p;
    const int tid = threadIdx.x, lane = tid & 31, wid = tid >> 5;
    const int g = lane >> 2, t = lane & 3;
    const int mt0 = (wid & 3) * 2, nt0 = (wid >> 2) * 8;
    const int mtg = blockIdx.x * 8 + mt0;
    const int ntg = blockIdx.y * 16 + nt0;
    const uint32_t* pa = Ap + (size_t)mtg * KT * 128 + lane * 4;
    const uint32_t* pb = Bp + (size_t)ntg * KT * 64 + lane * 2;
    float c[2][8][4] = {};
#pragma unroll 4
    for (int kt = 0; kt < KT; kt++) {
        uint4 a0 = *(const uint4*)(pa + kt * 128);
        uint4 a1 = *(const uint4*)(pa + (KT + kt) * 128);
        uint2 b[8];
#pragma unroll
        for (int in = 0; in < 8; in++)
            b[in] = *(const uint2*)(pb + ((size_t)in * KT + kt) * 64);
#pragma unroll
        for (int in = 0; in < 8; in++) {
            mma_f16(c[0][in], a0, b[in]);
            mma_f16(c[1][in], a1, b[in]);
        }
    }
    if (EPI == 0) {
        __half* C = (c_sel == 0) ? g_xlh : g_xrh;
#pragma unroll
        for (int im = 0; im < 2; im++) {
            int r0 = blockIdx.x * 128 + (mt0 + im) * 16 + g;
#pragma unroll
            for (int in = 0; in < 8; in++) {
                int col = blockIdx.y * 128 + (nt0 + in) * 8 + t * 2;
                float2 bv = *(const float2*)&bias[col];
                if (r0 < M)
                    *(uint32_t*)&C[(size_t)r0 * Nc + col] =
                        h2(c[im][in][0] + bv.x, c[im][in][1] + bv.y);
                if (r0 + 8 < M)
                    *(uint32_t*)&C[(size_t)(r0 + 8) * Nc + col] =
                        h2(c[im][in][2] + bv.x, c[im][in][3] + bv.y);
            }
        }
    } else if (EPI == 2) {
#pragma unroll
        for (int im = 0; im < 2; im++) {
            int r0 = blockIdx.x * 128 + (mt0 + im) * 16 + g;
#pragma unroll
            for (int in = 0; in < 8; in++) {
                int col = blockIdx.y * 128 + (nt0 + in) * 8 + t * 2;
                float2 bv = *(const float2*)&bias[col];
                if (r0 < M)
                    *(float2*)&g_ff[(size_t)r0 * Nc + col] =
                        make_float2(c[im][in][0] + bv.x, c[im][in][1] + bv.y);
                if (r0 + 8 < M)
                    *(float2*)&g_ff[(size_t)(r0 + 8) * Nc + col] =
                        make_float2(c[im][in][2] + bv.x, c[im][in][3] + bv.y);
            }
        }
    } else {
        __half* hp = (__half*)g_hidp;
#pragma unroll
        for (int im = 0; im < 2; im++) {
#pragma unroll
            for (int in = 0; in < 8; in++) {
                int nb = blockIdx.y * 128 + (nt0 + in) * 8 + t * 2;
                float2 bv = *(const float2*)&bias[nb];
#pragma unroll
                for (int jj = 0; jj < 4; jj++) {
                    float v = c[im][in][jj] + ((jj & 1) ? bv.y : bv.x);
                    v = fmaxf(v, 0.0f);
                    int r = (blockIdx.x * 8 + mt0 + im) * 16 + g + 8 * (jj >> 1);
                    int n = nb + (jj & 1);
                    int mt = r >> 4, mm = r & 15, gg = mm & 7, b0 = mm >> 3;
                    int ktn = n >> 4, nn = n & 15;
                    int tt = (nn >> 1) & 3, b1 = (nn >> 3) & 1;
                    hp[(((size_t)mt * 32 + ktn) * 128 +
                        (gg * 4 + tt) * 4 + b0 + 2 * b1) * 2 + (nn & 1)]
                        = __float2half_rn(v);
                }
            }
        }
    }
}

// ---------------- fused score + aggregation + residual + LN1 ----------------
// Warp per node; CSR-ordered edges in chunks of 16 via m16n8k16 (ea@We),
// score -> exp -> per-head register accumulation; epilogue does
// new_x/denominator, residual, LN1, and fp16 x1 packing. No g_as, no second
// xl gather pass, xr loaded per-node (L1-hot re-reads within node).
__global__ __launch_bounds__(256)
void fused_edge_kernel(const float* __restrict__ eattr,
                       const float* __restrict__ att,
                       const float* __restrict__ x,
                       const float* __restrict__ bias,
                       const float* __restrict__ g1,
                       const float* __restrict__ be1) {
    int w = (blockIdx.x * blockDim.x + threadIdx.x) >> 5;
    int lane = threadIdx.x & 31;
    if (w >= NN) return;
    const int g = lane >> 2, t = lane & 3;
    const int beg = g_off[w], end = g_off[w + 1];
    float acc[32];                 // cols {in*8+2t, +1}, partial over g-groups
#pragma unroll
    for (int i = 0; i < 32; i++) acc[i] = 0.f;
    float dsum[8];
#pragma unroll
    for (int h = 0; h < 8; h++) dsum[h] = 0.f;

    for (int c0 = beg; c0 < end; c0 += 16) {
        int sg0 = c0 + g, sg1 = c0 + g + 8;
        bool v0 = sg0 < end, v1 = sg1 < end;
        int src0 = v0 ? g_csrc[sg0] : 0;
        int src1 = v1 ? g_csrc[sg1] : 0;
        int e0 = v0 ? g_eid[sg0] : EE;
        int e1 = v1 ? g_eid[sg1] : EE;
        const float* rp0 = (e0 < EE) ? eattr + (size_t)e0 * DEE
                                     : g_la + (size_t)(e0 - EE) * DEE;
        const float* rp1 = (e1 < EE) ? eattr + (size_t)e1 * DEE
                                     : g_la + (size_t)(e1 - EE) * DEE;
        uint4 afr[2];
#pragma unroll
        for (int kt = 0; kt < 2; kt++) {
            int k = kt * 16 + 2 * t;
            float2 pa0 = *(const float2*)&rp0[k];
            float2 pa1 = *(const float2*)&rp1[k];
            float2 pa2 = *(const float2*)&rp0[k + 8];
            float2 pa3 = *(const float2*)&rp1[k + 8];
            afr[kt].x = h2(pa0.x, pa0.y);
            afr[kt].y = h2(pa1.x, pa1.y);
            afr[kt].z = h2(pa2.x, pa2.y);
            afr[kt].w = h2(pa3.x, pa3.y);
        }
        float p0[8] = {}, p1[8] = {};
#pragma unroll
        for (int in = 0; in < 16; in++) {
            float c4[4] = {};
            uint2 b0 = *(const uint2*)&g_wep[((size_t)in * 2 + 0) * 64 + lane * 2];
            uint2 b1 = *(const uint2*)&g_wep[((size_t)in * 2 + 1) * 64 + lane * 2];
            mma_f16(c4, afr[0], b0);
            mma_f16(c4, afr[1], b1);
            int col = in * 8 + t * 2;
            float2 atv = *(const float2*)&att[col];
            float2 xr2 = __half22float2(*(const __half2*)&g_xrh[(size_t)w * DXX + col]);
            float2 xa = __half22float2(*(const __half2*)&g_xlh[(size_t)src0 * DXX + col]);
            float2 xb = __half22float2(*(const __half2*)&g_xlh[(size_t)src1 * DXX + col]);
            int h = in >> 1;
            float u;
            u = c4[0] + xa.x + xr2.x; u = u > 0.f ? u : NEGS * u; p0[h] = fmaf(u, atv.x, p0[h]);
            u = c4[1] + xa.y + xr2.y; u = u > 0.f ? u : NEGS * u; p0[h] = fmaf(u, atv.y, p0[h]);
            u = c4[2] + xb.x + xr2.x; u = u > 0.f ? u : NEGS * u; p1[h] = fmaf(u, atv.x, p1[h]);
            u = c4[3] + xb.y + xr2.y; u = u > 0.f ? u : NEGS * u; p1[h] = fmaf(u, atv.y, p1[h]);
        }
#pragma unroll
        for (int h = 0; h < 8; h++) {
            p0[h] += __shfl_xor_sync(0xffffffffu, p0[h], 1);
            p0[h] += __shfl_xor_sync(0xffffffffu, p0[h], 2);
            p1[h] += __shfl_xor_sync(0xffffffffu, p1[h], 1);
            p1[h] += __shfl_xor_sync(0xffffffffu, p1[h], 2);
            p0[h] = v0 ? expf(p0[h]) : 0.f;     // scores tiny -> no max-shift
            p1[h] = v1 ? expf(p1[h]) : 0.f;
            dsum[h] += p0[h] + p1[h];
        }
        // weighted accumulation; xl rows re-read (L1-hot from score loop)
#pragma unroll
        for (int in = 0; in < 16; in++) {
            int col = in * 8 + t * 2;
            float2 xa = __half22float2(*(const __half2*)&g_xlh[(size_t)src0 * DXX + col]);
            float2 xb = __half22float2(*(const __half2*)&g_xlh[(size_t)src1 * DXX + col]);
            int h = in >> 1;
            acc[2 * in]     = fmaf(p0[h], xa.x, fmaf(p1[h], xb.x, acc[2 * in]));
            acc[2 * in + 1] = fmaf(p0[h], xa.y, fmaf(p1[h], xb.y, acc[2 * in + 1]));
        }
    }
    // reduce over the 8 g-groups (lane bits 2..4)
#pragma unroll
    for (int ofs = 4; ofs <= 16; ofs <<= 1) {
#pragma unroll
        for (int i = 0; i < 32; i++) acc[i] += __shfl_xor_sync(0xffffffffu, acc[i], ofs);
#pragma unroll
        for (int h = 0; h < 8; h++) dsum[h] += __shfl_xor_sync(0xffffffffu, dsum[h], ofs);
    }
    // y = x + accum/denom + bias ; LN1 (each col counted 8x across g-copies)
    float y[32];
    float s = 0.f, s2 = 0.f;
#pragma unroll
    for (int in = 0; in < 16; in++) {
        int col = in * 8 + t * 2;
        float2 xv = *(const float2*)&x[(size_t)w * DXX + col];
        float2 bv = *(const float2*)&bias[col];
        float inv_d = 1.0f / dsum[in >> 1];
        float ya = xv.x + fmaf(acc[2 * in], inv_d, bv.x);
        float yb = xv.y + fmaf(acc[2 * in + 1], inv_d, bv.y);
        y[2 * in] = ya; y[2 * in + 1] = yb;
        s += ya + yb;
        s2 = fmaf(ya, ya, fmaf(yb, yb, s2));
    }
#pragma unroll
    for (int o = 16; o; o >>= 1) {
        s += __shfl_xor_sync(0xffffffffu, s, o);
        s2 += __shfl_xor_sync(0xffffffffu, s2, o);
    }
    float mean = s * (1.0f / (DXX * 8));
    float var = s2 * (1.0f / (DXX * 8)) - mean * mean;
    float inv = rsqrtf(var + EPSLN);
    if (g == 0) {   // lanes 0..3 hold the reduced copies; write 128 cols
        int mt = w >> 4, mm = w & 15, gg = mm & 7, b0 = mm >> 3;
#pragma unroll
        for (int in = 0; in < 16; in++) {
            int col = in * 8 + t * 2;
            float2 gv = *(const float2*)&g1[col];
            float2 ev = *(const float2*)&be1[col];
            float oa = fmaf((y[2 * in] - mean) * inv, gv.x, ev.x);
            float ob = fmaf((y[2 * in + 1] - mean) * inv, gv.y, ev.y);
            *(float2*)&g_x1[(size_t)w * DXX + col] = make_float2(oa, ob);
            // fp16 fragment-packed write for FF1's A operand (pair of cols)
            int ktn = col >> 4, c = (col >> 2) & 3, half = (col >> 1) & 1;
            int tt = (2 * c + half) & 3, jj = (2 * c + half) >> 2;
            g_x1p[((size_t)mt * 8 + ktn) * 128 + (gg * 4 + tt) * 4 + b0 + 2 * jj]
                = h2(oa, ob);
        }
    }
}

// ---------------- node epilogue 2 -------------------------------------------
__global__ __launch_bounds__(256)
void node_ln2_kernel(float* __restrict__ out,
                     const float* __restrict__ g2, const float* __restrict__ be2) {
    int w = (blockIdx.x * blockDim.x + threadIdx.x) >> 5;
    int lane = threadIdx.x & 31;
    if (w >= NN) return;
    size_t off = (size_t)w * DXX + lane * 4;
    float4 xv = *(const float4*)&g_x1[off];
    float4 fv = *(const float4*)&g_ff[off];
    float y0 = xv.x + fv.x;
    float y1 = xv.y + fv.y;
    float y2 = xv.z + fv.z;
    float y3 = xv.w + fv.w;
    float s = y0 + y1 + y2 + y3;
    float s2 = fmaf(y0, y0, fmaf(y1, y1, fmaf(y2, y2, y3 * y3)));
#pragma unroll
    for (int o = 16; o; o >>= 1) {
        s += __shfl_xor_sync(0xffffffffu, s, o);
        s2 += __shfl_xor_sync(0xffffffffu, s2, o);
    }
    float mean = s * (1.0f / DXX);
    float var = s2 * (1.0f / DXX) - mean * mean;
    float inv = rsqrtf(var + EPSLN);
    float4 gv = *(const float4*)&g2[lane * 4];
    float4 ev = *(const float4*)&be2[lane * 4];
    float4 o4;
    o4.x = fmaf((y0 - mean) * inv, gv.x, ev.x);
    o4.y = fmaf((y1 - mean) * inv, gv.y, ev.y);
    o4.z = fmaf((y2 - mean) * inv, gv.z, ev.z);
    o4.w = fmaf((y3 - mean) * inv, gv.w, ev.w);
    *(float4*)&out[off] = o4;
}

// ---------------------------------------------------------------------------
extern "C" void kernel_launch(void* const* d_in, const int* in_sizes, int n_in,
                              void* d_out, int out_size) {
    const float* x     = (const float*)d_in[0];
    const int*   ei    = (const int*)d_in[1];     // int32 (JAX x64 disabled)
    const float* eattr = (const float*)d_in[2];
    const float* Wl    = (const float*)d_in[3];
    const float* bl    = (const float*)d_in[4];
    const float* Wr    = (const float*)d_in[5];
    const float* br    = (const float*)d_in[6];
    const float* We    = (const float*)d_in[7];
    const float* att   = (const float*)d_in[8];
    const float* bias  = (const float*)d_in[9];
    const float* W1    = (const float*)d_in[10];
    const float* b1    = (const float*)d_in[11];
    const float* W2    = (const float*)d_in[12];
    const float* b2    = (const float*)d_in[13];
    const float* g1    = (const float*)d_in[14];
    const float* be1   = (const float*)d_in[15];
    const float* g2    = (const float*)d_in[16];
    const float* be2   = (const float*)d_in[17];
    float* out = (float*)d_out;

    zero_kernel<<<(NN * DEE + 255) / 256, 256>>>();

    pack_x_kernel<<<(MPAD * 32 + 255) / 256, 256>>>(x);
    pack_w_kernel<<<(DXX * DXX + 255) / 256, 256>>>(Wl, DXX, DXX, 0);
    pack_w_kernel<<<(DXX * DXX + 255) / 256, 256>>>(Wr, DXX, DXX, 1);
    pack_w_kernel<<<(DXX * FFF + 255) / 256, 256>>>(W1, DXX, FFF, 2);
    pack_w_kernel<<<(FFF * DXX + 255) / 256, 256>>>(W2, FFF, DXX, 3);
    pack_w_kernel<<<(DEE * DXX + 255) / 256, 256>>>(We, DEE, DXX, 4);

    deg_kernel<<<(EE * 8 + 255) / 256, 256>>>(ei, eattr);
    div_kernel<<<(NN * DEE + 255) / 256, 256>>>();
    scan_kernel<<<1, 1024>>>();
    scatter_kernel<<<(ETOT + 255) / 256, 256>>>(ei);

    // xl = x@Wl + bl ; xr = x@Wr + br  (fp16 tensor cores, half output)
    {
        dim3 grid(MT_N, 1);
        fgemm<8, 0><<<grid, 256>>>(0, 0, 0, bl, NN, DXX);
        fgemm<8, 0><<<grid, 256>>>(0, 1, 1, br, NN, DXX);
    }

    // fused score + aggregation + residual + LN1 (+pack x1)
    fused_edge_kernel<<<(NN * 32 + 255) / 256, 256>>>(eattr, att, x, bias, g1, be1);

    // FFN: hid = relu(x1@W1+b1) packed fp16 ; ff = hid@W2+b2 (f32 out)
    {
        dim3 grid1(MT_N, FFF / 128);
        fgemm<8, 1><<<grid1, 256>>>(1, 2, 0, b1, NN, FFF);
        dim3 grid2(MT_N, 1);
        fgemm<32, 2><<<grid2, 256>>>(2, 3, 2, b2, NN, DXX);
    }

    // residual + LN2 -> out
    node_ln2_kernel<<<(NN * 32 + 255) / 256, 256>>>(out, g2, be2);
}